// round 2
// baseline (speedup 1.0000x reference)
#include <cuda_runtime.h>

// Problem constants
#define Bn   1024
#define Hn   256
#define Gn   768      // 3*H
#define On   512
#define Tn   60
#define Cc   15
#define TB   8        // samples per CTA tile
#define MAXT 143      // upper bound on sum_c ceil(n_c/TB) = floor((1024+15*7)/8)=141, padded

// Device scratch (allocation-free rule: static __device__ arrays)
__device__ float g_Wi_t[Cc * Hn * Gn];   // [c][k][g] transposed W_ih
__device__ float g_Wh_t[Cc * Hn * Gn];   // [c][k][g] transposed W_hh
__device__ float g_Wc_t[Cc * Hn * On];   // [c][k][o] transposed Wc
__device__ int   g_perm[Bn];
__device__ int   g_tile_cam[MAXT];
__device__ int   g_tile_start[MAXT];
__device__ int   g_tile_cnt[MAXT];

typedef unsigned long long u64;

__device__ __forceinline__ u64 pack2(float a, float b) {
    u64 r;
    asm("mov.b64 %0, {%1, %2};" : "=l"(r)
        : "r"(__float_as_uint(a)), "r"(__float_as_uint(b)));
    return r;
}
__device__ __forceinline__ void fma2(u64 &d, u64 a, u64 b) {
    // d += a * b  (packed 2x fp32)
    asm("fma.rn.f32x2 %0, %1, %2, %0;" : "+l"(d) : "l"(a), "l"(b));
}
__device__ __forceinline__ float2 unpack2(u64 v) {
    unsigned lo, hi;
    asm("mov.b64 {%0, %1}, %2;" : "=r"(lo), "=r"(hi) : "l"(v));
    return make_float2(__uint_as_float(lo), __uint_as_float(hi));
}
__device__ __forceinline__ float sigmoidf_(float v) {
    return 1.0f / (1.0f + __expf(-v));
}

// ---------------------------------------------------------------------------
// Kernel 0: counting-sort samples by camera, build tile table.
// ---------------------------------------------------------------------------
__global__ void bucket_kernel(const int* __restrict__ cam) {
    __shared__ int cnts[Cc], offs[Cc], curs[Cc];
    int tid = threadIdx.x;
    if (tid < Cc) cnts[tid] = 0;
    __syncthreads();
    for (int b = tid; b < Bn; b += blockDim.x)
        atomicAdd(&cnts[cam[b]], 1);
    __syncthreads();
    if (tid == 0) {
        int o = 0;
        for (int c = 0; c < Cc; c++) { offs[c] = o; curs[c] = o; o += cnts[c]; }
    }
    __syncthreads();
    for (int b = tid; b < Bn; b += blockDim.x) {
        int p = atomicAdd(&curs[cam[b]], 1);
        g_perm[p] = b;
    }
    __syncthreads();
    if (tid == 0) {
        int t = 0;
        for (int c = 0; c < Cc; c++) {
            for (int s = 0; s < cnts[c]; s += TB) {
                g_tile_cam[t]   = c;
                g_tile_start[t] = offs[c] + s;
                g_tile_cnt[t]   = min(TB, cnts[c] - s);
                t++;
            }
        }
        for (; t < MAXT; t++) g_tile_cnt[t] = 0;
    }
}

// ---------------------------------------------------------------------------
// Kernel 1: transpose weights to k-major (coalesced column loads in GEMM).
// ---------------------------------------------------------------------------
__global__ void transpose_kernel(const float* __restrict__ Wi,
                                 const float* __restrict__ Wh,
                                 const float* __restrict__ Wc) {
    int idx    = blockIdx.x * blockDim.x + threadIdx.x;
    int stride = gridDim.x * blockDim.x;
    const int totA = Cc * Hn * Gn;
    for (int i = idx; i < totA; i += stride) {
        int g = i % Gn;
        int k = (i / Gn) % Hn;
        int c = i / (Gn * Hn);
        g_Wi_t[i] = Wi[(c * Gn + g) * Hn + k];
        g_Wh_t[i] = Wh[(c * Gn + g) * Hn + k];
    }
    const int totC = Cc * Hn * On;
    for (int i = idx; i < totC; i += stride) {
        int o = i % On;
        int k = (i / On) % Hn;
        int c = i / (On * Hn);
        g_Wc_t[i] = Wc[(c * On + o) * Hn + k];
    }
}

// ---------------------------------------------------------------------------
// Main persistent kernel: one CTA per 8-sample same-camera tile. Runs the
// full T=60 recurrence with no inter-CTA sync. Thread `tid` owns gate
// columns (tid, tid+256, tid+512) and output columns (tid, tid+256).
// ---------------------------------------------------------------------------
__global__ void __launch_bounds__(256, 1)
gru_main_kernel(const float* __restrict__ x,
                const float* __restrict__ b_ih,
                const float* __restrict__ b_hh,
                const float* __restrict__ bc,
                float* __restrict__ out) {
    __shared__ __align__(16) float sh_h[Hn][TB];
    __shared__ __align__(16) float sh_x[Hn][TB];
    __shared__ int sh_samp[TB];

    const int tile = blockIdx.x;
    const int cnt  = g_tile_cnt[tile];
    if (cnt == 0) return;
    const int cam   = g_tile_cam[tile];
    const int start = g_tile_start[tile];
    const int tid   = threadIdx.x;

    if (tid < TB) sh_samp[tid] = (tid < cnt) ? g_perm[start + tid] : 0;
    __syncthreads();

    // Load x transposed into smem (zero-pad missing samples), init h = 0.
    for (int i = tid; i < Hn * TB; i += 256) {
        int s = i % TB, k = i / TB;
        sh_x[k][s] = (s < cnt) ? x[sh_samp[s] * Hn + k] : 0.0f;
        sh_h[k][s] = 0.0f;
    }
    __syncthreads();

    // gi = x @ Wi^T + b_ih, held in registers (constant over T).
    // r/z gates also fold b_hh; the n gate keeps b_hh_n separate
    // because reference computes n = tanh(gi_n + r*(h@Wh_n + b_hh_n)).
    float giR[TB], giZ[TB], giN[TB];
    {
        float aR[TB], aZ[TB], aN[TB];
#pragma unroll
        for (int s = 0; s < TB; s++) { aR[s] = 0.f; aZ[s] = 0.f; aN[s] = 0.f; }
        const float* wi = g_Wi_t + cam * Hn * Gn;
#pragma unroll 4
        for (int k = 0; k < Hn; k++) {
            float w0 = wi[tid], w1 = wi[256 + tid], w2 = wi[512 + tid];
#pragma unroll
            for (int s = 0; s < TB; s++) {
                float hv = sh_x[k][s];
                aR[s] += w0 * hv;
                aZ[s] += w1 * hv;
                aN[s] += w2 * hv;
            }
            wi += Gn;
        }
        float br = b_ih[cam * Gn + tid]       + b_hh[cam * Gn + tid];
        float bz = b_ih[cam * Gn + 256 + tid] + b_hh[cam * Gn + 256 + tid];
        float bn = b_ih[cam * Gn + 512 + tid];
#pragma unroll
        for (int s = 0; s < TB; s++) {
            giR[s] = aR[s] + br;
            giZ[s] = aZ[s] + bz;
            giN[s] = aN[s] + bn;
        }
    }
    const float bhn = b_hh[cam * Gn + 512 + tid];
    const float bc0 = bc[cam * On + tid];
    const float bc1 = bc[cam * On + 256 + tid];

    int obase[TB];
#pragma unroll
    for (int s = 0; s < TB; s++) obase[s] = sh_samp[s] * (On * Tn);

    const float* Wh = g_Wh_t + cam * Hn * Gn;
    const float* Wc = g_Wc_t + cam * Hn * On;

    for (int t = 0; t < Tn; t++) {
        // ---- Phase A: gh = h @ Wh^T, gate update -> h_new -------------
        u64 accR[TB / 2], accZ[TB / 2], accN[TB / 2];
#pragma unroll
        for (int p = 0; p < TB / 2; p++) { accR[p] = 0; accZ[p] = 0; accN[p] = 0; }
        {
            const float* wp = Wh;
#pragma unroll 4
            for (int k = 0; k < Hn; k++) {
                float wr = wp[tid], wz = wp[256 + tid], wn = wp[512 + tid];
                u64 wr2 = pack2(wr, wr), wz2 = pack2(wz, wz), wn2 = pack2(wn, wn);
                const u64* hp = reinterpret_cast<const u64*>(&sh_h[k][0]);
#pragma unroll
                for (int p = 0; p < TB / 2; p++) {
                    u64 hv = hp[p];
                    fma2(accR[p], wr2, hv);
                    fma2(accZ[p], wz2, hv);
                    fma2(accN[p], wn2, hv);
                }
                wp += Gn;
            }
        }
        float hnew[TB];
#pragma unroll
        for (int p = 0; p < TB / 2; p++) {
            float2 aR = unpack2(accR[p]);
            float2 aZ = unpack2(accZ[p]);
            float2 aN = unpack2(accN[p]);
            int s0 = 2 * p, s1 = 2 * p + 1;
            {
                float r = sigmoidf_(giR[s0] + aR.x);
                float z = sigmoidf_(giZ[s0] + aZ.x);
                float n = tanhf(giN[s0] + r * (aN.x + bhn));
                hnew[s0] = (1.0f - z) * n + z * sh_h[tid][s0];
            }
            {
                float r = sigmoidf_(giR[s1] + aR.y);
                float z = sigmoidf_(giZ[s1] + aZ.y);
                float n = tanhf(giN[s1] + r * (aN.y + bhn));
                hnew[s1] = (1.0f - z) * n + z * sh_h[tid][s1];
            }
        }
        __syncthreads();   // all reads of old h (accum + gate) complete
#pragma unroll
        for (int s = 0; s < TB; s++) sh_h[tid][s] = hnew[s];
        __syncthreads();   // h_new visible to all threads

        // ---- Phase B: out = sigmoid(h_new @ Wc^T + bc) -----------------
        u64 a0[TB / 2], a1[TB / 2];
#pragma unroll
        for (int p = 0; p < TB / 2; p++) { a0[p] = 0; a1[p] = 0; }
        {
            const float* wp = Wc;
#pragma unroll 4
            for (int k = 0; k < Hn; k++) {
                float w0 = wp[tid], w1 = wp[256 + tid];
                u64 w02 = pack2(w0, w0), w12 = pack2(w1, w1);
                const u64* hp = reinterpret_cast<const u64*>(&sh_h[k][0]);
#pragma unroll
                for (int p = 0; p < TB / 2; p++) {
                    u64 hv = hp[p];
                    fma2(a0[p], w02, hv);
                    fma2(a1[p], w12, hv);
                }
                wp += On;
            }
        }
#pragma unroll
        for (int p = 0; p < TB / 2; p++) {
            float2 v0 = unpack2(a0[p]);
            float2 v1 = unpack2(a1[p]);
            int s0 = 2 * p, s1 = 2 * p + 1;
            if (s0 < cnt) {
                out[obase[s0] + tid * Tn + t]         = sigmoidf_(v0.x + bc0);
                out[obase[s0] + (256 + tid) * Tn + t] = sigmoidf_(v1.x + bc1);
            }
            if (s1 < cnt) {
                out[obase[s1] + tid * Tn + t]         = sigmoidf_(v0.y + bc0);
                out[obase[s1] + (256 + tid) * Tn + t] = sigmoidf_(v1.y + bc1);
            }
        }
        // Next iteration's Phase A reads h then hits the first barrier
        // before any rewrite, so Phase B's reads are protected.
    }
}

// ---------------------------------------------------------------------------
extern "C" void kernel_launch(void* const* d_in, const int* in_sizes, int n_in,
                              void* d_out, int out_size) {
    const float* x    = (const float*)d_in[0];
    const int*   cam  = (const int*)  d_in[1];
    const float* W_ih = (const float*)d_in[2];
    const float* W_hh = (const float*)d_in[3];
    const float* b_ih = (const float*)d_in[4];
    const float* b_hh = (const float*)d_in[5];
    const float* Wc   = (const float*)d_in[6];
    const float* bc   = (const float*)d_in[7];
    float* out = (float*)d_out;

    bucket_kernel<<<1, 256>>>(cam);
    transpose_kernel<<<1024, 256>>>(W_ih, W_hh, Wc);
    gru_main_kernel<<<MAXT, 256>>>(x, b_ih, b_hh, bc, out);
}

// round 3
// speedup vs baseline: 1.6536x; 1.6536x over previous
#include <cuda_runtime.h>

// Problem constants
#define Bn   1024
#define Hn   256
#define Gn   768      // 3*H
#define On   512
#define Tn   60
#define Cc   15
#define TB   10       // samples per CTA tile
#define K4   64       // Hn/4
#define MAXT 116      // sum_c ceil(n_c/TB) <= floor((1024+15*9)/10)=115, padded

// Device scratch (allocation-free rule: static __device__ arrays)
// Packed k4-interleaved layouts: W_p[((c*K4 + k4)*COLS + g)*4 + j] = W[c][g][4*k4+j]
__device__ float g_Wi_p[Cc * K4 * Gn * 4];
__device__ float g_Wh_p[Cc * K4 * Gn * 4];
__device__ float g_Wc_p[Cc * K4 * On * 4];
__device__ int   g_perm[Bn];
__device__ int   g_tile_cam[MAXT];
__device__ int   g_tile_start[MAXT];
__device__ int   g_tile_cnt[MAXT];

typedef unsigned long long u64;

__device__ __forceinline__ u64 pack2(float a, float b) {
    u64 r;
    asm("mov.b64 %0, {%1, %2};" : "=l"(r)
        : "r"(__float_as_uint(a)), "r"(__float_as_uint(b)));
    return r;
}
__device__ __forceinline__ void fma2(u64 &d, u64 a, u64 b) {
    asm("fma.rn.f32x2 %0, %1, %2, %0;" : "+l"(d) : "l"(a), "l"(b));
}
__device__ __forceinline__ float2 unpack2(u64 v) {
    unsigned lo, hi;
    asm("mov.b64 {%0, %1}, %2;" : "=r"(lo), "=r"(hi) : "l"(v));
    return make_float2(__uint_as_float(lo), __uint_as_float(hi));
}
__device__ __forceinline__ float sigf(float v) {
    return 1.0f / (1.0f + __expf(-v));   // safe at +-inf
}
__device__ __forceinline__ float tanh_f(float v) {
    return 2.0f * sigf(2.0f * v) - 1.0f;
}

// ---------------------------------------------------------------------------
// Kernel 0: counting-sort samples by camera, build tile table.
// ---------------------------------------------------------------------------
__global__ void bucket_kernel(const int* __restrict__ cam) {
    __shared__ int cnts[Cc], offs[Cc], curs[Cc];
    int tid = threadIdx.x;
    if (tid < Cc) cnts[tid] = 0;
    __syncthreads();
    for (int b = tid; b < Bn; b += blockDim.x)
        atomicAdd(&cnts[cam[b]], 1);
    __syncthreads();
    if (tid == 0) {
        int o = 0;
        for (int c = 0; c < Cc; c++) { offs[c] = o; curs[c] = o; o += cnts[c]; }
    }
    __syncthreads();
    for (int b = tid; b < Bn; b += blockDim.x) {
        int p = atomicAdd(&curs[cam[b]], 1);
        g_perm[p] = b;
    }
    __syncthreads();
    if (tid == 0) {
        int t = 0;
        for (int c = 0; c < Cc; c++) {
            for (int s = 0; s < cnts[c]; s += TB) {
                g_tile_cam[t]   = c;
                g_tile_start[t] = offs[c] + s;
                g_tile_cnt[t]   = min(TB, cnts[c] - s);
                t++;
            }
        }
        for (; t < MAXT; t++) g_tile_cnt[t] = 0;
    }
}

// ---------------------------------------------------------------------------
// Kernel 1: repack weights into k4-interleaved float4 layout.
// ---------------------------------------------------------------------------
__global__ void transpose_kernel(const float* __restrict__ Wi,
                                 const float* __restrict__ Wh,
                                 const float* __restrict__ Wc) {
    int idx    = blockIdx.x * blockDim.x + threadIdx.x;
    int stride = gridDim.x * blockDim.x;
    const int totA = Cc * K4 * Gn * 4;
    for (int i = idx; i < totA; i += stride) {
        int j  = i & 3;
        int g  = (i >> 2) % Gn;
        int k4 = ((i >> 2) / Gn) % K4;
        int c  = i / (4 * Gn * K4);
        int k  = 4 * k4 + j;
        g_Wi_p[i] = Wi[(c * Gn + g) * Hn + k];
        g_Wh_p[i] = Wh[(c * Gn + g) * Hn + k];
    }
    const int totC = Cc * K4 * On * 4;
    for (int i = idx; i < totC; i += stride) {
        int j  = i & 3;
        int o  = (i >> 2) % On;
        int k4 = ((i >> 2) / On) % K4;
        int c  = i / (4 * On * K4);
        int k  = 4 * k4 + j;
        g_Wc_p[i] = Wc[(c * On + o) * Hn + k];
    }
}

// ---------------------------------------------------------------------------
// Main persistent kernel: one CTA per TB-sample same-camera tile.
// 512 threads, warp-specialized pipeline:
//   warps 0-7  (A): iter i computes h_{i+1} from h_i        (for i < T)
//   warps 8-15 (B): iter i computes out_{i-1} from h_i      (for i > 0)
// Both only READ buf[i&1] (= h_i); A WRITES buf[1-(i&1)] (= h_{i+1}).
// One __syncthreads per iteration.
// ---------------------------------------------------------------------------
__global__ void __launch_bounds__(512, 1)
gru_main_kernel(const float* __restrict__ x,
                const float* __restrict__ b_ih,
                const float* __restrict__ b_hh,
                const float* __restrict__ bc,
                float* __restrict__ out) {
    extern __shared__ float sm[];
    float* sh_h  = sm;                 // [2][Hn][TB]   (2*2560 floats)
    float* sh_x  = sm + 2 * Hn * TB;   // [Hn][TB]      (2560 floats)
    float* sh_gi = sm + 3 * Hn * TB;   // [3][256][TB]  (7680 floats)
    int*   sh_samp = (int*)(sm + 6 * Hn * TB);

    const int tile = blockIdx.x;
    const int cnt  = g_tile_cnt[tile];
    if (cnt == 0) return;
    const int cam   = g_tile_cam[tile];
    const int start = g_tile_start[tile];
    const int tid   = threadIdx.x;

    if (tid < TB) sh_samp[tid] = (tid < cnt) ? g_perm[start + tid] : 0;
    __syncthreads();

    // Init: x transposed into smem (zero-pad missing samples), h buffer0 = 0.
    for (int i = tid; i < Hn * TB; i += 512) {
        int s = i % TB, k = i / TB;
        sh_x[k * TB + s] = (s < cnt) ? x[sh_samp[s] * Hn + k] : 0.0f;
        sh_h[i] = 0.0f;
    }
    __syncthreads();

    // ---- per-group setup --------------------------------------------------
    float bhn = 0.0f, bc0 = 0.0f, bc1 = 0.0f;
    int   ob[TB];

    if (tid < 256) {
        // A-group: compute gi = x @ Wi^T + b_ih (+ b_hh folded for r,z),
        // store to smem (thread-private slice -> no barrier needed).
        const int lt = tid;
        float aR[TB], aZ[TB], aN[TB];
#pragma unroll
        for (int s = 0; s < TB; s++) { aR[s] = 0.f; aZ[s] = 0.f; aN[s] = 0.f; }
        const float4* w = ((const float4*)g_Wi_p) + (size_t)cam * K4 * Gn;
        for (int k4 = 0; k4 < K4; k4++) {
            float4 w0 = w[lt], w1 = w[256 + lt], w2 = w[512 + lt];
            const float* f0 = (const float*)&w0;
            const float* f1 = (const float*)&w1;
            const float* f2 = (const float*)&w2;
#pragma unroll
            for (int j = 0; j < 4; j++) {
                const float* xk = &sh_x[(4 * k4 + j) * TB];
#pragma unroll
                for (int s = 0; s < TB; s++) {
                    float xv = xk[s];
                    aR[s] += f0[j] * xv;
                    aZ[s] += f1[j] * xv;
                    aN[s] += f2[j] * xv;
                }
            }
            w += Gn;
        }
        float br = b_ih[cam * Gn + lt]       + b_hh[cam * Gn + lt];
        float bz = b_ih[cam * Gn + 256 + lt] + b_hh[cam * Gn + 256 + lt];
        float bn = b_ih[cam * Gn + 512 + lt];
#pragma unroll
        for (int s = 0; s < TB; s++) {
            sh_gi[0 * 256 * TB + lt * TB + s] = aR[s] + br;
            sh_gi[1 * 256 * TB + lt * TB + s] = aZ[s] + bz;
            sh_gi[2 * 256 * TB + lt * TB + s] = aN[s] + bn;
        }
        bhn = b_hh[cam * Gn + 512 + lt];
    } else {
        const int lb = tid - 256;
        bc0 = bc[cam * On + lb];
        bc1 = bc[cam * On + 256 + lb];
#pragma unroll
        for (int s = 0; s < TB; s++) ob[s] = sh_samp[s] * (On * Tn);
    }

    const float4* whp = ((const float4*)g_Wh_p) + (size_t)cam * K4 * Gn;
    const float4* wcp = ((const float4*)g_Wc_p) + (size_t)cam * K4 * On;

    // ---- pipelined main loop: T+1 iterations ------------------------------
    for (int i = 0; i <= Tn; i++) {
        const int p = i & 1;
        const float* hb = sh_h + p * (Hn * TB);         // h_i (read-only)
        float*       hw = sh_h + (1 - p) * (Hn * TB);   // h_{i+1} (A writes)

        if (tid < 256) {
            if (i < Tn) {
                const int lt = tid;
                u64 aR[5], aZ[5], aN[5];
#pragma unroll
                for (int q = 0; q < 5; q++) { aR[q] = 0; aZ[q] = 0; aN[q] = 0; }
                const float4* w = whp;
#pragma unroll 2
                for (int k4 = 0; k4 < K4; k4++) {
                    float4 wr = w[lt], wz = w[256 + lt], wn = w[512 + lt];
                    w += Gn;
                    const float* fr = (const float*)&wr;
                    const float* fz = (const float*)&wz;
                    const float* fn = (const float*)&wn;
#pragma unroll
                    for (int j = 0; j < 4; j++) {
                        const u64* hp = (const u64*)(hb + (4 * k4 + j) * TB);
                        u64 r2 = pack2(fr[j], fr[j]);
                        u64 z2 = pack2(fz[j], fz[j]);
                        u64 n2 = pack2(fn[j], fn[j]);
#pragma unroll
                        for (int q = 0; q < 5; q++) {
                            u64 hv = hp[q];
                            fma2(aR[q], r2, hv);
                            fma2(aZ[q], z2, hv);
                            fma2(aN[q], n2, hv);
                        }
                    }
                }
                // Gate epilogue -> h_{i+1}
                const float* hold = hb + lt * TB;
                float*       hnew = hw + lt * TB;
                const float* giR = &sh_gi[0 * 256 * TB + lt * TB];
                const float* giZ = &sh_gi[1 * 256 * TB + lt * TB];
                const float* giN = &sh_gi[2 * 256 * TB + lt * TB];
#pragma unroll
                for (int q = 0; q < 5; q++) {
                    float2 vR = unpack2(aR[q]);
                    float2 vZ = unpack2(aZ[q]);
                    float2 vN = unpack2(aN[q]);
                    int s0 = 2 * q, s1 = s0 + 1;
                    {
                        float r = sigf(giR[s0] + vR.x);
                        float z = sigf(giZ[s0] + vZ.x);
                        float n = tanh_f(giN[s0] + r * (vN.x + bhn));
                        hnew[s0] = (1.0f - z) * n + z * hold[s0];
                    }
                    {
                        float r = sigf(giR[s1] + vR.y);
                        float z = sigf(giZ[s1] + vZ.y);
                        float n = tanh_f(giN[s1] + r * (vN.y + bhn));
                        hnew[s1] = (1.0f - z) * n + z * hold[s1];
                    }
                }
            }
        } else {
            if (i > 0) {
                const int lb = tid - 256;
                const int t  = i - 1;
                u64 a0[5], a1[5];
#pragma unroll
                for (int q = 0; q < 5; q++) { a0[q] = 0; a1[q] = 0; }
                const float4* w = wcp;
#pragma unroll 2
                for (int k4 = 0; k4 < K4; k4++) {
                    float4 w0 = w[lb], w1 = w[256 + lb];
                    w += On;
                    const float* f0 = (const float*)&w0;
                    const float* f1 = (const float*)&w1;
#pragma unroll
                    for (int j = 0; j < 4; j++) {
                        const u64* hp = (const u64*)(hb + (4 * k4 + j) * TB);
                        u64 p0 = pack2(f0[j], f0[j]);
                        u64 p1 = pack2(f1[j], f1[j]);
#pragma unroll
                        for (int q = 0; q < 5; q++) {
                            u64 hv = hp[q];
                            fma2(a0[q], p0, hv);
                            fma2(a1[q], p1, hv);
                        }
                    }
                }
#pragma unroll
                for (int q = 0; q < 5; q++) {
                    float2 v0 = unpack2(a0[q]);
                    float2 v1 = unpack2(a1[q]);
                    int s0 = 2 * q, s1 = s0 + 1;
                    if (s0 < cnt) {
                        out[ob[s0] + lb * Tn + t]         = sigf(v0.x + bc0);
                        out[ob[s0] + (256 + lb) * Tn + t] = sigf(v1.x + bc1);
                    }
                    if (s1 < cnt) {
                        out[ob[s1] + lb * Tn + t]         = sigf(v0.y + bc0);
                        out[ob[s1] + (256 + lb) * Tn + t] = sigf(v1.y + bc1);
                    }
                }
            }
        }
        __syncthreads();   // publish h_{i+1}; retire reads of h_i
    }
}

// ---------------------------------------------------------------------------
extern "C" void kernel_launch(void* const* d_in, const int* in_sizes, int n_in,
                              void* d_out, int out_size) {
    const float* x    = (const float*)d_in[0];
    const int*   cam  = (const int*)  d_in[1];
    const float* W_ih = (const float*)d_in[2];
    const float* W_hh = (const float*)d_in[3];
    const float* b_ih = (const float*)d_in[4];
    const float* b_hh = (const float*)d_in[5];
    const float* Wc   = (const float*)d_in[6];
    const float* bc   = (const float*)d_in[7];
    float* out = (float*)d_out;

    const size_t smem = (size_t)(6 * Hn * TB) * sizeof(float) + 16 * sizeof(int);
    cudaFuncSetAttribute(gru_main_kernel,
                         cudaFuncAttributeMaxDynamicSharedMemorySize, (int)smem);

    bucket_kernel<<<1, 256>>>(cam);
    transpose_kernel<<<2048, 256>>>(W_ih, W_hh, Wc);
    gru_main_kernel<<<MAXT, 512, smem>>>(x, b_ih, b_hh, bc, out);
}